// round 1
// baseline (speedup 1.0000x reference)
#include <cuda_runtime.h>
#include <math.h>

#define cB 4
#define cL 512
#define cD 512
#define cH 16
#define cKH 32
#define cFF 2048
#define cNL 8
#define cND 14
#define cM 512
#define SCALEF 0.17677669529663687f  // 1/sqrt(32)

// ------------------------- scratch (static device globals; no allocs) ---------
__device__ float g_h [cB*cL*cD];
__device__ float g_q [cB*cL*cD];
__device__ float g_k [cB*cL*cD];
__device__ float g_v [cB*cL*cD];
__device__ float g_z [cB*cL*cD];
__device__ float g_o [cB*cL*cD];
__device__ float g_h2[cB*cL*cD];
__device__ float g_f [cB*cL*cFF];
__device__ float g_e [(size_t)cB*cH*cL*cL];           // scores / attention probs (64MB)
__device__ float g_qE  [cB*cH*cL*cND];
__device__ float g_kE  [cB*cH*cL*cND];
__device__ float g_abin[cB*cH*cL*cND];
__device__ unsigned char g_didx[cB*cL*cL];
__device__ float g_Vsum[cND*cKH];
__device__ float g_sumKkr[cND];

// ------------------------- distance bucketize -------------------------------
__global__ void didx_kernel(const float* __restrict__ dist) {
    int i = blockIdx.x * blockDim.x + threadIdx.x;
    float d = dist[i];
    int idx = 0;
#pragma unroll
    for (int j = 1; j <= 14; j++) idx += (10.0f * (float)j < d) ? 1 : 0;
    if (idx > 13) idx = 13;
    g_didx[i] = (unsigned char)idx;
}

// ------------------------- embedding gather ---------------------------------
__global__ void embed_kernel(const int* __restrict__ ct, const float* __restrict__ emb) {
    int row = blockIdx.x;                 // b*L + l
    int c0  = ct[row];
    for (int c = threadIdx.x; c < cD; c += blockDim.x)
        g_h[(size_t)row * cD + c] = emb[(size_t)c0 * cD + c];
}

// ------------------------- tiny precompute: Vsum, sumKkr --------------------
__global__ void prep_kernel(const float* __restrict__ Kkr,
                            const float* __restrict__ Vqk,
                            const float* __restrict__ Vqr,
                            const float* __restrict__ Vkr) {
    int t = threadIdx.x;
    if (t < cND * cKH) g_Vsum[t] = Vqk[t] + Vqr[t] + Vkr[t];
    if (t < cND) {
        float s = 0.f;
        for (int k = 0; k < cKH; k++) s += Kkr[t * cKH + k];
        g_sumKkr[t] = s;
    }
}

// ------------------------- generic tiled SGEMM: C = A*B + bias (opt gelu) ---
// A[M,K] row-major, B[K,N] row-major, bias[N]. M,N multiples of 64, K of 16.
__global__ void sgemm_bias(const float* __restrict__ A, const float* __restrict__ Bm,
                           const float* __restrict__ bias, float* __restrict__ C,
                           int Md, int Nd, int Kd, int act) {
    __shared__ float As[16][65];
    __shared__ float Bs[16][65];
    int t  = threadIdx.x;
    int tx = t % 16, ty = t / 16;
    int m0 = blockIdx.y * 64, n0 = blockIdx.x * 64;
    float acc[4][4] = {};
    for (int k0 = 0; k0 < Kd; k0 += 16) {
#pragma unroll
        for (int r = 0; r < 4; r++) {
            int m = r * 16 + (t / 16);
            int kk = t % 16;
            As[kk][m] = A[(size_t)(m0 + m) * Kd + k0 + kk];
        }
#pragma unroll
        for (int r = 0; r < 4; r++) {
            int kk = r * 4 + (t / 64);
            int n  = t % 64;
            Bs[kk][n] = Bm[(size_t)(k0 + kk) * Nd + n0 + n];
        }
        __syncthreads();
#pragma unroll
        for (int kk = 0; kk < 16; kk++) {
            float a[4], bb[4];
#pragma unroll
            for (int i = 0; i < 4; i++) a[i] = As[kk][ty + 16 * i];
#pragma unroll
            for (int j = 0; j < 4; j++) bb[j] = Bs[kk][tx + 16 * j];
#pragma unroll
            for (int i = 0; i < 4; i++)
#pragma unroll
                for (int j = 0; j < 4; j++) acc[i][j] += a[i] * bb[j];
        }
        __syncthreads();
    }
#pragma unroll
    for (int i = 0; i < 4; i++) {
#pragma unroll
        for (int j = 0; j < 4; j++) {
            int row = m0 + ty + 16 * i;
            int col = n0 + tx + 16 * j;
            float v = acc[i][j] + bias[col];
            if (act == 1) v = 0.5f * v * (1.0f + erff(v * 0.70710678118654752f));
            C[(size_t)row * Nd + col] = v;
        }
    }
}

// ------------------------- qE / kE : tiny per-row dots with 14 bucket rows --
__global__ void qke_kernel(const float* __restrict__ Kqk, const float* __restrict__ Kqr) {
    __shared__ float sq[cD], sk[cD];
    __shared__ float sKa[cND * cKH], sKb[cND * cKH];
    int bl = blockIdx.x;  // b*L + l
    int t  = threadIdx.x; // 256
    for (int c = t; c < cD; c += 256) {
        sq[c] = g_q[(size_t)bl * cD + c];
        sk[c] = g_k[(size_t)bl * cD + c];
    }
    for (int c = t; c < cND * cKH; c += 256) { sKa[c] = Kqk[c]; sKb[c] = Kqr[c]; }
    __syncthreads();
    if (t < cH * cND) {
        int h = t / cND, d = t % cND;
        float s1 = 0.f, s2 = 0.f;
#pragma unroll
        for (int k = 0; k < cKH; k++) {
            s1 += sq[h * cKH + k] * sKa[d * cKH + k];
            s2 += sk[h * cKH + k] * sKb[d * cKH + k];
        }
        int b = bl / cL, l = bl % cL;
        size_t off = ((size_t)(b * cH + (size_t)h) * cL + l) * cND + d;
        g_qE[off] = s1;
        g_kE[off] = s2;
    }
}

// ------------------------- attention scores (incl. bucket biases, scaled) ---
__global__ void scores_kernel() {
    int bh = blockIdx.z;
    int b  = bh / cH, h = bh % cH;
    int l0 = blockIdx.y * 64, x0 = blockIdx.x * 64;
    __shared__ float Qs[32][65], Ks[32][65];
    __shared__ float sQE[64][15], sKE[64][15];
    __shared__ float sKr[cND];
    __shared__ unsigned char sD[64][64];
    int t = threadIdx.x;
#pragma unroll
    for (int r = 0; r < 8; r++) {
        int i = r * 8 + (t / 32);
        int k = t % 32;
        Qs[k][i] = g_q[(size_t)(b * cL + l0 + i) * cD + h * cKH + k];
        Ks[k][i] = g_k[(size_t)(b * cL + x0 + i) * cD + h * cKH + k];
    }
    for (int idx = t; idx < 64 * cND; idx += 256) {
        int i = idx / cND, d = idx % cND;
        sQE[i][d] = g_qE[((size_t)bh * cL + l0 + i) * cND + d];
        sKE[i][d] = g_kE[((size_t)bh * cL + x0 + i) * cND + d];
    }
    if (t < cND) sKr[t] = g_sumKkr[t];
    for (int idx = t; idx < 64 * 64; idx += 256) {
        int i = idx / 64, j = idx % 64;
        sD[i][j] = g_didx[(size_t)(b * cL + l0 + i) * cL + x0 + j];
    }
    __syncthreads();
    int tx = t % 16, ty = t / 16;
    float acc[4][4] = {};
#pragma unroll
    for (int k = 0; k < 32; k++) {
        float a[4], bb[4];
#pragma unroll
        for (int i = 0; i < 4; i++) a[i] = Qs[k][ty + 16 * i];
#pragma unroll
        for (int j = 0; j < 4; j++) bb[j] = Ks[k][tx + 16 * j];
#pragma unroll
        for (int i = 0; i < 4; i++)
#pragma unroll
            for (int j = 0; j < 4; j++) acc[i][j] += a[i] * bb[j];
    }
#pragma unroll
    for (int i = 0; i < 4; i++) {
#pragma unroll
        for (int j = 0; j < 4; j++) {
            int li = ty + 16 * i, xj = tx + 16 * j;
            int d = sD[li][xj];
            float e = (acc[i][j] + sQE[li][d] + sKE[xj][d] + sKr[d]) * SCALEF;
            g_e[((size_t)bh * cL + l0 + li) * cL + x0 + xj] = e;
        }
    }
}

// ------------------------- softmax over last dim + bucket histogram ----------
__global__ void softmax_kernel() {
    int row = blockIdx.x;            // (b*H+h)*L + l
    int b = row / (cH * cL);
    int l = row % cL;
    float* e = g_e + (size_t)row * cL;
    const unsigned char* dd = g_didx + (size_t)(b * cL + l) * cL;
    int t = threadIdx.x;             // 128
    float v[4]; int di[4];
    float mx = -1e30f;
#pragma unroll
    for (int r = 0; r < 4; r++) {
        int c = t + 128 * r;
        v[r] = e[c];
        di[r] = dd[c];
        mx = fmaxf(mx, v[r]);
    }
    __shared__ float red[128];
    red[t] = mx; __syncthreads();
#pragma unroll
    for (int s = 64; s > 0; s >>= 1) { if (t < s) red[t] = fmaxf(red[t], red[t + s]); __syncthreads(); }
    mx = red[0]; __syncthreads();
    float sum = 0.f;
#pragma unroll
    for (int r = 0; r < 4; r++) { v[r] = __expf(v[r] - mx); sum += v[r]; }
    red[t] = sum; __syncthreads();
#pragma unroll
    for (int s = 64; s > 0; s >>= 1) { if (t < s) red[t] += red[t + s]; __syncthreads(); }
    float inv = 1.0f / red[0];
#pragma unroll
    for (int r = 0; r < 4; r++) { v[r] *= inv; e[t + 128 * r] = v[r]; }
    // deterministic bucket histogram of attention mass
    __shared__ float wsum[4][cND];
    int wid = t >> 5, lid = t & 31;
    for (int d = 0; d < cND; d++) {
        float p = 0.f;
#pragma unroll
        for (int r = 0; r < 4; r++) p += (di[r] == d) ? v[r] : 0.f;
#pragma unroll
        for (int o = 16; o > 0; o >>= 1) p += __shfl_down_sync(0xffffffffu, p, o);
        if (lid == 0) wsum[wid][d] = p;
    }
    __syncthreads();
    if (t < cND)
        g_abin[(size_t)row * cND + t] = wsum[0][t] + wsum[1][t] + wsum[2][t] + wsum[3][t];
}

// ------------------------- z = a@v + abin@Vsum ------------------------------
__global__ void attn_z_kernel() {
    int bh = blockIdx.y;
    int b = bh / cH, h = bh % cH;
    int l0 = blockIdx.x * 64;
    __shared__ float As[64][33];
    __shared__ float Vs[32][33];
    int t = threadIdx.x, tx = t & 31, ty = t >> 5;  // ty 0..7
    float acc[8] = {};
    const float* arow = g_e + ((size_t)bh * cL + l0) * cL;
    for (int x0 = 0; x0 < cL; x0 += 32) {
#pragma unroll
        for (int r = 0; r < 8; r++) {
            int i = r * 8 + ty;
            As[i][tx] = arow[(size_t)i * cL + x0 + tx];
        }
#pragma unroll
        for (int r = 0; r < 4; r++) {
            int i = r * 8 + ty;
            Vs[i][tx] = g_v[(size_t)(b * cL + x0 + i) * cD + h * cKH + tx];
        }
        __syncthreads();
#pragma unroll
        for (int x = 0; x < 32; x++) {
            float vb = Vs[x][tx];
#pragma unroll
            for (int i = 0; i < 8; i++) acc[i] += As[i * 8 + ty][x] * vb;
        }
        __syncthreads();
    }
    __shared__ float sAb[64][15];
    __shared__ float sVs[cND][32];
    for (int idx = t; idx < 64 * cND; idx += 256) {
        int i = idx / cND, d = idx % cND;
        sAb[i][d] = g_abin[((size_t)bh * cL + l0 + i) * cND + d];
    }
    for (int idx = t; idx < cND * cKH; idx += 256)
        sVs[idx / 32][idx % 32] = g_Vsum[idx];
    __syncthreads();
#pragma unroll
    for (int i = 0; i < 8; i++) {
        int li = i * 8 + ty;
        float s = acc[i];
#pragma unroll
        for (int d = 0; d < cND; d++) s += sAb[li][d] * sVs[d][tx];
        g_z[(size_t)(b * cL + l0 + li) * cD + h * cKH + tx] = s;
    }
}

// ------------------------- layernorm of (X + R) -----------------------------
__global__ void ln_kernel(const float* __restrict__ X, const float* __restrict__ R,
                          const float* __restrict__ gg, const float* __restrict__ bb,
                          float* __restrict__ out) {
    int row = blockIdx.x, t = threadIdx.x;  // 128 threads
    float lv[4];
    float s = 0.f;
#pragma unroll
    for (int r = 0; r < 4; r++) {
        int c = t + 128 * r;
        lv[r] = X[(size_t)row * cD + c] + R[(size_t)row * cD + c];
        s += lv[r];
    }
    __shared__ float red[128];
    red[t] = s; __syncthreads();
#pragma unroll
    for (int st = 64; st > 0; st >>= 1) { if (t < st) red[t] += red[t + st]; __syncthreads(); }
    float mu = red[0] * (1.0f / cD);
    __syncthreads();
    float vs = 0.f;
#pragma unroll
    for (int r = 0; r < 4; r++) { float d = lv[r] - mu; vs += d * d; }
    red[t] = vs; __syncthreads();
#pragma unroll
    for (int st = 64; st > 0; st >>= 1) { if (t < st) red[t] += red[t + st]; __syncthreads(); }
    float inv = rsqrtf(red[0] * (1.0f / cD) + 1e-5f);
#pragma unroll
    for (int r = 0; r < 4; r++) {
        int c = t + 128 * r;
        out[(size_t)row * cD + c] = (lv[r] - mu) * inv * gg[c] + bb[c];
    }
}

// ------------------------- head: pooled sum -> MLP -> out[b] ----------------
__global__ void head_kernel(const float* __restrict__ Wm1, const float* __restrict__ bm1,
                            const float* __restrict__ Wm2, const float* __restrict__ bm2,
                            float* __restrict__ out) {
    int b = blockIdx.x, t = threadIdx.x;  // 512 threads
    __shared__ float pooled[cD];
    float s = 0.f;
    for (int l = 0; l < cL; l++) s += g_h[(size_t)(b * cL + l) * cD + t];
    pooled[t] = s;
    __syncthreads();
    float r = bm1[t];
    for (int d = 0; d < cD; d++) r += pooled[d] * Wm1[(size_t)d * cM + t];
    r = fmaxf(r, 0.f);
    __shared__ float red[512];
    red[t] = r * Wm2[t];
    __syncthreads();
#pragma unroll
    for (int st = 256; st > 0; st >>= 1) { if (t < st) red[t] += red[t + st]; __syncthreads(); }
    if (t == 0) out[b] = red[0] + bm2[0];
}

// ===========================================================================
extern "C" void kernel_launch(void* const* d_in, const int* in_sizes, int n_in,
                              void* d_out, int out_size) {
    const int*   cell_types = (const int*)  d_in[0];
    const float* distances  = (const float*)d_in[1];
    const float* cell_emb   = (const float*)d_in[2];
    const float* Kqk = (const float*)d_in[3];
    const float* Kqr = (const float*)d_in[4];
    const float* Kkr = (const float*)d_in[5];
    const float* Vqk = (const float*)d_in[6];
    const float* Vqr = (const float*)d_in[7];
    const float* Vkr = (const float*)d_in[8];

    int iWq = 9, ibq, iWk, ibk, iWv, ibv, iWo, ibo;
    if (in_sizes[10] == cNL * cD) {  // interleaved (reference-signature) order
        ibq = 10; iWk = 11; ibk = 12; iWv = 13; ibv = 14; iWo = 15; ibo = 16;
    } else {                          // grouped (dict-insertion) order
        iWk = 10; iWv = 11; iWo = 12; ibq = 13; ibk = 14; ibv = 15; ibo = 16;
    }
    const float* Wq = (const float*)d_in[iWq];
    const float* bq = (const float*)d_in[ibq];
    const float* Wk = (const float*)d_in[iWk];
    const float* bk = (const float*)d_in[ibk];
    const float* Wv = (const float*)d_in[iWv];
    const float* bv = (const float*)d_in[ibv];
    const float* Wo = (const float*)d_in[iWo];
    const float* bo = (const float*)d_in[ibo];
    const float* W1  = (const float*)d_in[17];
    const float* b1  = (const float*)d_in[18];
    const float* W2  = (const float*)d_in[19];
    const float* b2  = (const float*)d_in[20];
    const float* g1  = (const float*)d_in[21];
    const float* be1 = (const float*)d_in[22];
    const float* g2  = (const float*)d_in[23];
    const float* be2 = (const float*)d_in[24];
    const float* Wm1 = (const float*)d_in[25];
    const float* bm1 = (const float*)d_in[26];
    const float* Wm2 = (const float*)d_in[27];
    const float* bm2 = (const float*)d_in[28];
    float* out = (float*)d_out;

    // resolve device scratch addresses (no allocations; just symbol lookups)
    float *p_h, *p_q, *p_k, *p_v, *p_z, *p_o, *p_h2, *p_f;
    cudaGetSymbolAddress((void**)&p_h,  g_h);
    cudaGetSymbolAddress((void**)&p_q,  g_q);
    cudaGetSymbolAddress((void**)&p_k,  g_k);
    cudaGetSymbolAddress((void**)&p_v,  g_v);
    cudaGetSymbolAddress((void**)&p_z,  g_z);
    cudaGetSymbolAddress((void**)&p_o,  g_o);
    cudaGetSymbolAddress((void**)&p_h2, g_h2);
    cudaGetSymbolAddress((void**)&p_f,  g_f);

    didx_kernel<<<(cB * cL * cL) / 256, 256>>>(distances);
    embed_kernel<<<cB * cL, 256>>>(cell_types, cell_emb);
    prep_kernel<<<1, 448>>>(Kkr, Vqk, Vqr, Vkr);

    dim3 gProj(cD / 64, (cB * cL) / 64);         // (8, 32)
    dim3 gFF1(cFF / 64, (cB * cL) / 64);         // (32, 32)
    dim3 gScores(cL / 64, cL / 64, cB * cH);     // (8, 8, 64)
    dim3 gZ(cL / 64, cB * cH);                   // (8, 64)

    for (int ly = 0; ly < cNL; ly++) {
        const float* wq  = Wq + (size_t)ly * cD * cD;
        const float* wk  = Wk + (size_t)ly * cD * cD;
        const float* wv  = Wv + (size_t)ly * cD * cD;
        const float* wo  = Wo + (size_t)ly * cD * cD;
        const float* bqp = bq + (size_t)ly * cD;
        const float* bkp = bk + (size_t)ly * cD;
        const float* bvp = bv + (size_t)ly * cD;
        const float* bop = bo + (size_t)ly * cD;
        const float* w1  = W1 + (size_t)ly * cD * cFF;
        const float* b1p = b1 + (size_t)ly * cFF;
        const float* w2  = W2 + (size_t)ly * cFF * cD;
        const float* b2p = b2 + (size_t)ly * cD;
        const float* g1p  = g1  + (size_t)ly * cD;
        const float* be1p = be1 + (size_t)ly * cD;
        const float* g2p  = g2  + (size_t)ly * cD;
        const float* be2p = be2 + (size_t)ly * cD;

        sgemm_bias<<<gProj, 256>>>(p_h, wq, bqp, p_q, cB * cL, cD, cD, 0);
        sgemm_bias<<<gProj, 256>>>(p_h, wk, bkp, p_k, cB * cL, cD, cD, 0);
        sgemm_bias<<<gProj, 256>>>(p_h, wv, bvp, p_v, cB * cL, cD, cD, 0);
        qke_kernel<<<cB * cL, 256>>>(Kqk, Kqr);
        scores_kernel<<<gScores, 256>>>();
        softmax_kernel<<<cB * cH * cL, 128>>>();
        attn_z_kernel<<<gZ, 256>>>();
        sgemm_bias<<<gProj, 256>>>(p_z, wo, bop, p_o, cB * cL, cD, cD, 0);
        ln_kernel<<<cB * cL, 128>>>(p_h, p_o, g1p, be1p, p_h2);
        sgemm_bias<<<gFF1, 256>>>(p_h2, w1, b1p, p_f, cB * cL, cFF, cD, 1);
        sgemm_bias<<<gProj, 256>>>(p_f, w2, b2p, p_o, cB * cL, cD, cFF, 0);
        ln_kernel<<<cB * cL, 128>>>(p_h2, p_o, g2p, be2p, p_h);
    }

    head_kernel<<<cB, 512>>>(Wm1, bm1, Wm2, bm2, out);
}

// round 2
// speedup vs baseline: 1.4518x; 1.4518x over previous
#include <cuda_runtime.h>
#include <math.h>

#define cB 4
#define cL 512
#define cD 512
#define cH 16
#define cKH 32
#define cFF 2048
#define cNL 8
#define cND 14
#define cM 512
#define cBL (cB*cL)
#define SCALEF 0.17677669529663687f  // 1/sqrt(32)

// ------------------------- scratch (static device globals) ------------------
__device__ float g_h [cBL*cD];
__device__ float g_q [cBL*cD];
__device__ float g_k [cBL*cD];
__device__ float g_v [cBL*cD];
__device__ float g_z [cBL*cD];
__device__ float g_o [cBL*cD];
__device__ float g_h2[cBL*cD];
__device__ float g_f [cBL*cFF];
__device__ float g_qE [cB*cH*cL*cND];
__device__ float g_kE [cB*cH*cL*cND];
__device__ unsigned char g_didx[cB*cL*cL];
__device__ float g_Vsum[cND*cKH];
__device__ float g_sumKkr[cND];

// ------------------------- distance bucketize -------------------------------
__global__ void didx_kernel(const float* __restrict__ dist) {
    int i = blockIdx.x * blockDim.x + threadIdx.x;
    float d = dist[i];
    int idx = 0;
#pragma unroll
    for (int j = 1; j <= 14; j++) idx += (10.0f * (float)j < d) ? 1 : 0;
    if (idx > 13) idx = 13;
    g_didx[i] = (unsigned char)idx;
}

// ------------------------- embedding gather ---------------------------------
__global__ void embed_kernel(const int* __restrict__ ct, const float* __restrict__ emb) {
    int row = blockIdx.x;
    int c0  = ct[row];
    for (int c = threadIdx.x; c < cD; c += blockDim.x)
        g_h[(size_t)row * cD + c] = emb[(size_t)c0 * cD + c];
}

// ------------------------- tiny precompute ----------------------------------
__global__ void prep_kernel(const float* __restrict__ Kkr,
                            const float* __restrict__ Vqk,
                            const float* __restrict__ Vqr,
                            const float* __restrict__ Vkr) {
    int t = threadIdx.x;
    if (t < cND * cKH) g_Vsum[t] = Vqk[t] + Vqr[t] + Vkr[t];
    if (t < cND) {
        float s = 0.f;
        for (int k = 0; k < cKH; k++) s += Kkr[t * cKH + k];
        g_sumKkr[t] = s;
    }
}

// ------------------------- high-throughput SGEMM ----------------------------
// C = A*B + bias, optional exact GELU. BM=128, TM=8 fixed. 256 threads.
struct GemmArgs3 {
    const float* A;
    const float* W0; const float* W1; const float* W2;
    const float* b0; const float* b1; const float* b2;
    float* C0; float* C1; float* C2;
};

template<int BN, int BK, int TN, bool GELU, bool TRIPLE>
__global__ __launch_bounds__(256) void gemm_kernel(GemmArgs3 args, int Md, int Nd, int Kd) {
    constexpr int BM = 128, TM = 8, THREADS = 256;
    constexpr int A_F4 = (BM * BK) / (THREADS * 4);   // 1 or 2
    constexpr int B_F4 = (BK * BN) / (THREADS * 4);   // 1

    const float* A = args.A;
    const float* W; const float* bias; float* C;
    if (TRIPLE) {
        int z = blockIdx.z;
        W    = (z == 0) ? args.W0 : (z == 1) ? args.W1 : args.W2;
        bias = (z == 0) ? args.b0 : (z == 1) ? args.b1 : args.b2;
        C    = (z == 0) ? args.C0 : (z == 1) ? args.C1 : args.C2;
    } else {
        W = args.W0; bias = args.b0; C = args.C0;
    }

    __shared__ float As[BK][BM];
    __shared__ float Bs[BK][BN];

    int t  = threadIdx.x;
    int tC = t % (BN / TN);   // 0..15
    int tR = t / (BN / TN);   // 0..15
    int m0 = blockIdx.y * BM, n0 = blockIdx.x * BN;

    float4 aReg[A_F4], bReg[B_F4];

    // ---- global loads (into regs) ----
    auto loadG = [&](int k0) {
#pragma unroll
        for (int it = 0; it < A_F4; it++) {
            int idx = t + it * THREADS;
            int row = idx / (BK / 4);
            int kc  = (idx % (BK / 4)) * 4;
            aReg[it] = *(const float4*)&A[(size_t)(m0 + row) * Kd + k0 + kc];
        }
#pragma unroll
        for (int it = 0; it < B_F4; it++) {
            int idx = t + it * THREADS;
            int row = idx / (BN / 4);
            int c   = (idx % (BN / 4)) * 4;
            bReg[it] = *(const float4*)&W[(size_t)(k0 + row) * Nd + n0 + c];
        }
    };
    auto storeS = [&]() {
#pragma unroll
        for (int it = 0; it < A_F4; it++) {
            int idx = t + it * THREADS;
            int row = idx / (BK / 4);
            int kc  = (idx % (BK / 4)) * 4;
            As[kc + 0][row] = aReg[it].x;
            As[kc + 1][row] = aReg[it].y;
            As[kc + 2][row] = aReg[it].z;
            As[kc + 3][row] = aReg[it].w;
        }
#pragma unroll
        for (int it = 0; it < B_F4; it++) {
            int idx = t + it * THREADS;
            int row = idx / (BN / 4);
            int c   = (idx % (BN / 4)) * 4;
            *(float4*)&Bs[row][c] = bReg[it];
        }
    };

    loadG(0); storeS();
    __syncthreads();

    float acc[TM][TN] = {};
    for (int k0 = 0; k0 < Kd; k0 += BK) {
        bool more = (k0 + BK < Kd);
        if (more) loadG(k0 + BK);
#pragma unroll
        for (int k = 0; k < BK; k++) {
            float a[TM], b[TN];
#pragma unroll
            for (int i = 0; i < TM; i++) a[i] = As[k][tR * TM + i];
#pragma unroll
            for (int j = 0; j < TN; j++) b[j] = Bs[k][tC * TN + j];
#pragma unroll
            for (int i = 0; i < TM; i++)
#pragma unroll
                for (int j = 0; j < TN; j++) acc[i][j] += a[i] * b[j];
        }
        if (more) {
            __syncthreads();
            storeS();
            __syncthreads();
        }
    }

    // ---- epilogue ----
    float bb[TN];
#pragma unroll
    for (int j = 0; j < TN; j++) bb[j] = bias[n0 + tC * TN + j];
#pragma unroll
    for (int i = 0; i < TM; i++) {
        int row = m0 + tR * TM + i;
#pragma unroll
        for (int j0 = 0; j0 < TN; j0 += 4) {
            float4 o;
            float* po = &o.x;
#pragma unroll
            for (int j = 0; j < 4; j++) {
                float v = acc[i][j0 + j] + bb[j0 + j];
                if (GELU) v = 0.5f * v * (1.0f + erff(v * 0.70710678118654752f));
                po[j] = v;
            }
            *(float4*)&C[(size_t)row * Nd + n0 + tC * TN + j0] = o;
        }
    }
}

// ------------------------- qE / kE ------------------------------------------
__global__ void qke_kernel(const float* __restrict__ Kqk, const float* __restrict__ Kqr) {
    __shared__ float sq[cD], sk[cD];
    __shared__ float sKa[cND * cKH], sKb[cND * cKH];
    int bl = blockIdx.x;
    int t  = threadIdx.x;
    for (int c = t; c < cD; c += 256) {
        sq[c] = g_q[(size_t)bl * cD + c];
        sk[c] = g_k[(size_t)bl * cD + c];
    }
    for (int c = t; c < cND * cKH; c += 256) { sKa[c] = Kqk[c]; sKb[c] = Kqr[c]; }
    __syncthreads();
    if (t < cH * cND) {
        int h = t / cND, d = t % cND;
        float s1 = 0.f, s2 = 0.f;
#pragma unroll
        for (int k = 0; k < cKH; k++) {
            s1 += sq[h * cKH + k] * sKa[d * cKH + k];
            s2 += sk[h * cKH + k] * sKb[d * cKH + k];
        }
        int b = bl / cL, l = bl % cL;
        size_t off = ((size_t)(b * cH + (size_t)h) * cL + l) * cND + d;
        g_qE[off] = s1;
        g_kE[off] = s2;
    }
}

// ------------------------- fused flash attention ----------------------------
// One block per (bh, 64-row l-tile). Full 64x512 score strip lives in smem.
// Phase 1: scores + bucket biases. Phase 2: softmax (exact max) + bucket hist.
// Phase 3: AV + hist*Vsum, normalized. All deterministic (no atomics).
#define SC_STRIDE 520
__global__ __launch_bounds__(256) void flash_attn_kernel() {
    extern __shared__ char smraw[];
    float* SC            = (float*)smraw;                 // 64*520
    unsigned char* DIDX  = (unsigned char*)(SC + 64 * SC_STRIDE); // 64*512 bytes
    float* QS   = (float*)(DIDX + 64 * 512);              // 32*65
    float* KS   = QS + 32 * 65;                           // 2112 floats (KS 32x65 / VS 64x33)
    float* QES  = KS + 2112;                              // 64*16 (reused: final hist)
    float* KES  = QES + 64 * 16;                          // 64*16
    float* HIST = KES + 64 * 16;                          // 16*256
    float* REDM = HIST + 16 * 256;                        // 256
    float* REDS = REDM + 256;                             // 256
    float* RINV = REDS + 256;                             // 64
    float* VSUM = RINV + 64;                              // 448
    float* SKR  = VSUM + 448;                             // 16

    int bh = blockIdx.y;
    int b  = bh >> 4, h = bh & 15;
    int l0 = blockIdx.x * 64;
    int t  = threadIdx.x;

    // ---- preload Q tile, qE, didx strip, Vsum, sumKkr ----
#pragma unroll
    for (int r = 0; r < 8; r++) {
        int l = r * 8 + (t >> 5), k = t & 31;
        QS[k * 65 + l] = g_q[(size_t)(b * cL + l0 + l) * cD + h * 32 + k];
    }
    for (int idx = t; idx < 64 * cND; idx += 256) {
        int l = idx / cND, d = idx % cND;
        QES[l * 16 + d] = g_qE[((size_t)bh * cL + l0 + l) * cND + d];
    }
    {
        const int4* src = (const int4*)(g_didx + ((size_t)b * cL + l0) * cL);
        for (int idx = t; idx < 2048; idx += 256) ((int4*)DIDX)[idx] = src[idx];
    }
    for (int idx = t; idx < cND * 32; idx += 256) VSUM[idx] = g_Vsum[idx];
    if (t < cND) SKR[t] = g_sumKkr[t];
    __syncthreads();

    // ---- phase 1: scores ----
    {
        int tx = t & 15, ty = t >> 4;
        for (int xt = 0; xt < 8; xt++) {
            int x0 = xt * 64;
#pragma unroll
            for (int r = 0; r < 8; r++) {
                int i = r * 8 + (t >> 5), k = t & 31;
                KS[k * 65 + i] = g_k[(size_t)(b * cL + x0 + i) * cD + h * 32 + k];
            }
            for (int idx = t; idx < 64 * cND; idx += 256) {
                int i2 = idx / cND, d = idx % cND;
                KES[i2 * 16 + d] = g_kE[((size_t)bh * cL + x0 + i2) * cND + d];
            }
            __syncthreads();
            float acc[4][4] = {};
#pragma unroll
            for (int k = 0; k < 32; k++) {
                float a[4], bb[4];
#pragma unroll
                for (int i = 0; i < 4; i++) a[i] = QS[k * 65 + ty + 16 * i];
#pragma unroll
                for (int j = 0; j < 4; j++) bb[j] = KS[k * 65 + tx + 16 * j];
#pragma unroll
                for (int i = 0; i < 4; i++)
#pragma unroll
                    for (int j = 0; j < 4; j++) acc[i][j] += a[i] * bb[j];
            }
#pragma unroll
            for (int i = 0; i < 4; i++)
#pragma unroll
                for (int j = 0; j < 4; j++) {
                    int li = ty + 16 * i, xj = tx + 16 * j;
                    int d = DIDX[li * 512 + x0 + xj];
                    SC[li * SC_STRIDE + x0 + xj] =
                        (acc[i][j] + QES[li * 16 + d] + KES[xj * 16 + d] + SKR[d]) * SCALEF;
                }
            __syncthreads();
        }
    }

    // ---- phase 2: softmax + bucket histogram (deterministic) ----
    {
        int r = t >> 2, j = t & 3;   // 4 threads per row, x = 4*i + j
        float m = -1e30f;
        for (int i = 0; i < 128; i++) m = fmaxf(m, SC[r * SC_STRIDE + 4 * i + j]);
        REDM[t] = m;
        __syncthreads();
        m = fmaxf(fmaxf(REDM[r * 4], REDM[r * 4 + 1]), fmaxf(REDM[r * 4 + 2], REDM[r * 4 + 3]));
#pragma unroll
        for (int d = 0; d < 16; d++) HIST[d * 256 + t] = 0.f;
        float s = 0.f;
        for (int i = 0; i < 128; i++) {
            int x = 4 * i + j;
            float p = __expf(SC[r * SC_STRIDE + x] - m);
            SC[r * SC_STRIDE + x] = p;
            s += p;
            int d = DIDX[r * 512 + x];
            HIST[d * 256 + t] += p;
        }
        REDS[t] = s;
        __syncthreads();
        if (t < 64) RINV[t] = 1.0f / (REDS[4 * t] + REDS[4 * t + 1] + REDS[4 * t + 2] + REDS[4 * t + 3]);
        for (int idx = t; idx < 64 * cND; idx += 256) {
            int d = idx >> 6, r2 = idx & 63;
            QES[r2 * 16 + d] = HIST[d * 256 + 4 * r2]     + HIST[d * 256 + 4 * r2 + 1]
                             + HIST[d * 256 + 4 * r2 + 2] + HIST[d * 256 + 4 * r2 + 3];
        }
        __syncthreads();
    }

    // ---- phase 3: z = (P@V + hist@Vsum) * rinv ----
    {
        int txk = t & 31, tyr = t >> 5;   // thread: rows {8i+tyr}, k-col txk
        float acc[8] = {};
        float* VS = KS;                   // reuse as [64][33]
        for (int xt = 0; xt < 8; xt++) {
            int x0 = xt * 64;
#pragma unroll
            for (int r = 0; r < 8; r++) {
                int i = r * 8 + tyr;
                VS[i * 33 + txk] = g_v[(size_t)(b * cL + x0 + i) * cD + h * 32 + txk];
            }
            __syncthreads();
#pragma unroll
            for (int xc = 0; xc < 16; xc++) {          // 4 x at a time via float4
                float4 a4[8];
#pragma unroll
                for (int i = 0; i < 8; i++)
                    a4[i] = *(const float4*)&SC[(i * 8 + tyr) * SC_STRIDE + x0 + xc * 4];
#pragma unroll
                for (int q = 0; q < 4; q++) {
                    float vb = VS[(xc * 4 + q) * 33 + txk];
                    const float* pa;
#pragma unroll
                    for (int i = 0; i < 8; i++) {
                        pa = &a4[i].x;
                        acc[i] += pa[q] * vb;
                    }
                }
            }
            __syncthreads();
        }
#pragma unroll
        for (int i = 0; i < 8; i++) {
            int l = i * 8 + tyr;
            float zv = acc[i];
#pragma unroll
            for (int d = 0; d < cND; d++) zv += QES[l * 16 + d] * VSUM[d * 32 + txk];
            g_z[(size_t)(b * cL + l0 + l) * cD + h * 32 + txk] = zv * RINV[l];
        }
    }
}

// ------------------------- layernorm of (X + R) -----------------------------
__global__ void ln_kernel(const float* __restrict__ X, const float* __restrict__ R,
                          const float* __restrict__ gg, const float* __restrict__ bb,
                          float* __restrict__ out) {
    int row = blockIdx.x, t = threadIdx.x;  // 128 threads
    float lv[4];
    float s = 0.f;
#pragma unroll
    for (int r = 0; r < 4; r++) {
        int c = t + 128 * r;
        lv[r] = X[(size_t)row * cD + c] + R[(size_t)row * cD + c];
        s += lv[r];
    }
    __shared__ float red[128];
    red[t] = s; __syncthreads();
#pragma unroll
    for (int st = 64; st > 0; st >>= 1) { if (t < st) red[t] += red[t + st]; __syncthreads(); }
    float mu = red[0] * (1.0f / cD);
    __syncthreads();
    float vs = 0.f;
#pragma unroll
    for (int r = 0; r < 4; r++) { float d = lv[r] - mu; vs += d * d; }
    red[t] = vs; __syncthreads();
#pragma unroll
    for (int st = 64; st > 0; st >>= 1) { if (t < st) red[t] += red[t + st]; __syncthreads(); }
    float inv = rsqrtf(red[0] * (1.0f / cD) + 1e-5f);
#pragma unroll
    for (int r = 0; r < 4; r++) {
        int c = t + 128 * r;
        out[(size_t)row * cD + c] = (lv[r] - mu) * inv * gg[c] + bb[c];
    }
}

// ------------------------- head ---------------------------------------------
__global__ void head_kernel(const float* __restrict__ Wm1, const float* __restrict__ bm1,
                            const float* __restrict__ Wm2, const float* __restrict__ bm2,
                            float* __restrict__ out) {
    int b = blockIdx.x, t = threadIdx.x;  // 512 threads
    __shared__ float pooled[cD];
    float s = 0.f;
    for (int l = 0; l < cL; l++) s += g_h[(size_t)(b * cL + l) * cD + t];
    pooled[t] = s;
    __syncthreads();
    float r = bm1[t];
    for (int d = 0; d < cD; d++) r += pooled[d] * Wm1[(size_t)d * cM + t];
    r = fmaxf(r, 0.f);
    __shared__ float red[512];
    red[t] = r * Wm2[t];
    __syncthreads();
#pragma unroll
    for (int st = 256; st > 0; st >>= 1) { if (t < st) red[t] += red[t + st]; __syncthreads(); }
    if (t == 0) out[b] = red[0] + bm2[0];
}

// ===========================================================================
extern "C" void kernel_launch(void* const* d_in, const int* in_sizes, int n_in,
                              void* d_out, int out_size) {
    const int*   cell_types = (const int*)  d_in[0];
    const float* distances  = (const float*)d_in[1];
    const float* cell_emb   = (const float*)d_in[2];
    const float* Kqk = (const float*)d_in[3];
    const float* Kqr = (const float*)d_in[4];
    const float* Kkr = (const float*)d_in[5];
    const float* Vqk = (const float*)d_in[6];
    const float* Vqr = (const float*)d_in[7];
    const float* Vkr = (const float*)d_in[8];

    int iWq = 9, ibq, iWk, ibk, iWv, ibv, iWo, ibo;
    if (in_sizes[10] == cNL * cD) {  // interleaved order
        ibq = 10; iWk = 11; ibk = 12; iWv = 13; ibv = 14; iWo = 15; ibo = 16;
    } else {                          // grouped order
        iWk = 10; iWv = 11; iWo = 12; ibq = 13; ibk = 14; ibv = 15; ibo = 16;
    }
    const float* Wq = (const float*)d_in[iWq];
    const float* bq = (const float*)d_in[ibq];
    const float* Wk = (const float*)d_in[iWk];
    const float* bk = (const float*)d_in[ibk];
    const float* Wv = (const float*)d_in[iWv];
    const float* bv = (const float*)d_in[ibv];
    const float* Wo = (const float*)d_in[iWo];
    const float* bo = (const float*)d_in[ibo];
    const float* W1  = (const float*)d_in[17];
    const float* b1  = (const float*)d_in[18];
    const float* W2  = (const float*)d_in[19];
    const float* b2  = (const float*)d_in[20];
    const float* g1  = (const float*)d_in[21];
    const float* be1 = (const float*)d_in[22];
    const float* g2  = (const float*)d_in[23];
    const float* be2 = (const float*)d_in[24];
    const float* Wm1 = (const float*)d_in[25];
    const float* bm1 = (const float*)d_in[26];
    const float* Wm2 = (const float*)d_in[27];
    const float* bm2 = (const float*)d_in[28];
    float* out = (float*)d_out;

    float *p_h, *p_q, *p_k, *p_v, *p_z, *p_o, *p_h2, *p_f;
    cudaGetSymbolAddress((void**)&p_h,  g_h);
    cudaGetSymbolAddress((void**)&p_q,  g_q);
    cudaGetSymbolAddress((void**)&p_k,  g_k);
    cudaGetSymbolAddress((void**)&p_v,  g_v);
    cudaGetSymbolAddress((void**)&p_z,  g_z);
    cudaGetSymbolAddress((void**)&p_o,  g_o);
    cudaGetSymbolAddress((void**)&p_h2, g_h2);
    cudaGetSymbolAddress((void**)&p_f,  g_f);

    // flash kernel smem opt-in (host-side attribute set; not a stream op)
    static const int FLASH_SMEM =
        (64 * SC_STRIDE) * 4 + 64 * 512 +
        (32 * 65 + 2112 + 64 * 16 + 64 * 16 + 16 * 256 + 256 + 256 + 64 + 448 + 16) * 4;
    cudaFuncSetAttribute(flash_attn_kernel,
                         cudaFuncAttributeMaxDynamicSharedMemorySize, FLASH_SMEM);

    didx_kernel<<<(cB * cL * cL) / 256, 256>>>(distances);
    embed_kernel<<<cBL, 256>>>(cell_types, cell_emb);
    prep_kernel<<<1, 448>>>(Kkr, Vqk, Vqr, Vkr);

    dim3 gQKV(cD / 128, cBL / 128, 3);      // (4,16,3) = 192 blocks
    dim3 gFF1(cFF / 128, cBL / 128);        // (16,16)  = 256 blocks
    dim3 gN64(cD / 64, cBL / 128);          // (8,16)   = 128 blocks
    dim3 gFlash(cL / 64, cB * cH);          // (8,64)   = 512 blocks

    for (int ly = 0; ly < cNL; ly++) {
        const float* wq  = Wq + (size_t)ly * cD * cD;
        const float* wk  = Wk + (size_t)ly * cD * cD;
        const float* wv  = Wv + (size_t)ly * cD * cD;
        const float* wo  = Wo + (size_t)ly * cD * cD;
        const float* bqp = bq + (size_t)ly * cD;
        const float* bkp = bk + (size_t)ly * cD;
        const float* bvp = bv + (size_t)ly * cD;
        const float* bop = bo + (size_t)ly * cD;
        const float* w1  = W1 + (size_t)ly * cD * cFF;
        const float* b1p = b1 + (size_t)ly * cFF;
        const float* w2  = W2 + (size_t)ly * cFF * cD;
        const float* b2p = b2 + (size_t)ly * cD;
        const float* g1p  = g1  + (size_t)ly * cD;
        const float* be1p = be1 + (size_t)ly * cD;
        const float* g2p  = g2  + (size_t)ly * cD;
        const float* be2p = be2 + (size_t)ly * cD;

        // fused QKV projection
        GemmArgs3 aQKV = { p_h, wq, wk, wv, bqp, bkp, bvp, p_q, p_k, p_v };
        gemm_kernel<128, 8, 8, false, true><<<gQKV, 256>>>(aQKV, cBL, cD, cD);

        qke_kernel<<<cBL, 256>>>(Kqk, Kqr);
        flash_attn_kernel<<<gFlash, 256, FLASH_SMEM>>>();

        GemmArgs3 aO = { p_z, wo, 0, 0, bop, 0, 0, p_o, 0, 0 };
        gemm_kernel<64, 16, 4, false, false><<<gN64, 256>>>(aO, cBL, cD, cD);
        ln_kernel<<<cBL, 128>>>(p_h, p_o, g1p, be1p, p_h2);

        GemmArgs3 aF1 = { p_h2, w1, 0, 0, b1p, 0, 0, p_f, 0, 0 };
        gemm_kernel<128, 8, 8, true, false><<<gFF1, 256>>>(aF1, cBL, cFF, cD);

        GemmArgs3 aF2 = { p_f, w2, 0, 0, b2p, 0, 0, p_o, 0, 0 };
        gemm_kernel<64, 16, 4, false, false><<<gN64, 256>>>(aF2, cBL, cD, cFF);

        ln_kernel<<<cBL, 128>>>(p_h2, p_o, g2p, be2p, p_h);
    }

    head_kernel<<<cB, 512>>>(Wm1, bm1, Wm2, bm2, out);
}